// round 4
// baseline (speedup 1.0000x reference)
#include <cuda_runtime.h>
#include <stdint.h>

// Binarized depthwise 3x3 conv, stride 1, SAME. x:(16,112,112,256) NHWC fp32,
// kernel:(3,3,256,1). out = sum of sign(x)*sign(k) over valid taps.
//
// bf16x2 math: pack 2 channels' fp32 high-halves into one reg (PRMT); per tap
// one LOP3 ((t & 0x80008000) ^ kp) yields bf16x2 of +-1.0 (or +-0.0 when the
// kp entry is zeroed for a missing border row); accumulate with add.rn.bf16x2
// (exact: |sum| <= 9 fits bf16 integers).
//
// ROW PAIRING: each block computes 2 adjacent output rows (h0, h0+1) from 4
// input rows -> 1.0 loads/output instead of 1.5, and 2x (not 3x) L2 read
// amplification. W split into 2 strips of 56 (grid stays 1792).
//
// Streaming column recurrence per output row (out[w] = q0(w-1)+q1(w)+q2(w+1)):
//   at column c: out[c-1] = A + q2(c); A = B + q1(c); B = q0(c)

#define NN 16
#define HH 112
#define WW 112
#define CC 256

__device__ __forceinline__ uint32_t badd(uint32_t a, uint32_t b) {
    uint32_t r;
    asm("add.rn.bf16x2 %0, %1, %2;" : "=r"(r) : "r"(a), "r"(b));
    return r;
}

#define TAPP(t, kp) ((((t) & 0x80008000u)) ^ (kp))

__device__ __forceinline__ uint32_t pack2(float2 v) {
    return __byte_perm(__float_as_uint(v.x), __float_as_uint(v.y), 0x7632);
}

__global__ __launch_bounds__(128, 8)
void bconv_kernel(const float* __restrict__ x,
                  const float* __restrict__ k,
                  float* __restrict__ out) {
    const int hpair = blockIdx.x >> 1;      // 0..55 -> output rows 2i, 2i+1
    const int strip = blockIdx.x & 1;       // W halves
    const int n = blockIdx.y;
    const int t = threadIdx.x;              // channel pair 0..127
    const int c0 = t * 2;

    const int h0 = hpair * 2;
    const bool top = (hpair == 0);          // output row h0 lacks its top tap
    const bool bot = (hpair == 55);         // output row h0+1 lacks bottom tap

    // Base kernel signs as bf16x2 of +-1.0 per channel pair.
    uint32_t kp[3][3];
#pragma unroll
    for (int kh = 0; kh < 3; ++kh)
#pragma unroll
        for (int kw = 0; kw < 3; ++kw) {
            const float2 kv = *reinterpret_cast<const float2*>(k + (kh * 3 + kw) * CC + c0);
            uint32_t s0 = (kv.x >= 0.0f) ? 0x3F80u : 0xBF80u;
            uint32_t s1 = (kv.y >= 0.0f) ? 0x3F80u : 0xBF80u;
            kp[kh][kw] = s0 | (s1 << 16);
        }
    // Border-zeroed variants (only differ at image top/bottom pairs).
    uint32_t kpA0[3], kpB2[3];
#pragma unroll
    for (int kw = 0; kw < 3; ++kw) {
        kpA0[kw] = top ? 0u : kp[0][kw];
        kpB2[kw] = bot ? 0u : kp[2][kw];
    }

    // 4 input rows: h0-1, h0, h0+1, h0+2 (clamped; contributions zeroed above).
    const int rm = top ? h0 : h0 - 1;
    const int rp = bot ? h0 + 1 : h0 + 2;
    const float* r0 = x + (((size_t)n * HH + rm    ) * WW) * CC + c0;
    const float* r1 = x + (((size_t)n * HH + h0    ) * WW) * CC + c0;
    const float* r2 = x + (((size_t)n * HH + h0 + 1) * WW) * CC + c0;
    const float* r3 = x + (((size_t)n * HH + rp    ) * WW) * CC + c0;
    float*       oA = out + (((size_t)n * HH + h0    ) * WW) * CC + c0;
    float*       oB = out + (((size_t)n * HH + h0 + 1) * WW) * CC + c0;

    const int ws = strip * (WW / 2);
    const int we = ws + (WW / 2);
    const int cbeg = (ws == 0) ? 0 : ws - 1;
    const int cend = (we == WW) ? WW - 1 : we;

    uint32_t AA = 0, BA = 0, AB = 0, BB = 0;

#pragma unroll 2
    for (int c = cbeg; c <= cend; ++c) {
        const uint32_t t0 = pack2(*reinterpret_cast<const float2*>(r0 + (size_t)c * CC));
        const uint32_t t1 = pack2(*reinterpret_cast<const float2*>(r1 + (size_t)c * CC));
        const uint32_t t2 = pack2(*reinterpret_cast<const float2*>(r2 + (size_t)c * CC));
        const uint32_t t3 = pack2(*reinterpret_cast<const float2*>(r3 + (size_t)c * CC));

        // Output row A: input rows (r0,r1,r2) with kh (0,1,2); kh0 may be zeroed.
        const uint32_t qA0 = badd(badd(TAPP(t0, kpA0[0]), TAPP(t1, kp[1][0])), TAPP(t2, kp[2][0]));
        const uint32_t qA1 = badd(badd(TAPP(t0, kpA0[1]), TAPP(t1, kp[1][1])), TAPP(t2, kp[2][1]));
        const uint32_t qA2 = badd(badd(TAPP(t0, kpA0[2]), TAPP(t1, kp[1][2])), TAPP(t2, kp[2][2]));
        // Output row B: input rows (r1,r2,r3) with kh (0,1,2); kh2 may be zeroed.
        const uint32_t qB0 = badd(badd(TAPP(t1, kp[0][0]), TAPP(t2, kp[1][0])), TAPP(t3, kpB2[0]));
        const uint32_t qB1 = badd(badd(TAPP(t1, kp[0][1]), TAPP(t2, kp[1][1])), TAPP(t3, kpB2[1]));
        const uint32_t qB2 = badd(badd(TAPP(t1, kp[0][2]), TAPP(t2, kp[1][2])), TAPP(t3, kpB2[2]));

        if (c > ws) {  // completes out[c-1] for this strip (uniform predicate)
            const uint32_t ovA = badd(AA, qA2);
            const uint32_t ovB = badd(AB, qB2);
            float2 o2;
            o2.x = __uint_as_float(ovA << 16);
            o2.y = __uint_as_float(ovA & 0xFFFF0000u);
            *reinterpret_cast<float2*>(oA + (size_t)(c - 1) * CC) = o2;
            o2.x = __uint_as_float(ovB << 16);
            o2.y = __uint_as_float(ovB & 0xFFFF0000u);
            *reinterpret_cast<float2*>(oB + (size_t)(c - 1) * CC) = o2;
        }
        AA = badd(BA, qA1); BA = qA0;
        AB = badd(BB, qB1); BB = qB0;
    }

    if (we == WW) {  // right border: out[111] = q0(110) + q1(111) = A
        float2 o2;
        o2.x = __uint_as_float(AA << 16);
        o2.y = __uint_as_float(AA & 0xFFFF0000u);
        *reinterpret_cast<float2*>(oA + (size_t)(WW - 1) * CC) = o2;
        o2.x = __uint_as_float(AB << 16);
        o2.y = __uint_as_float(AB & 0xFFFF0000u);
        *reinterpret_cast<float2*>(oB + (size_t)(WW - 1) * CC) = o2;
    }
}

extern "C" void kernel_launch(void* const* d_in, const int* in_sizes, int n_in,
                              void* d_out, int out_size) {
    const float* x = (const float*)d_in[0];
    const float* k = (const float*)d_in[1];
    float* out = (float*)d_out;
    dim3 grid(HH, NN);   // 112 = 56 row-pairs x 2 strips
    bconv_kernel<<<grid, 128>>>(x, k, out);
}